// round 14
// baseline (speedup 1.0000x reference)
#include <cuda_runtime.h>
#include <cuda_bf16.h>
#include <cstdint>

#define DIN   2048
#define DOUT  2048
#define MTOT  8192

// ---------------- scratch (static device globals; no allocation) ----------------
__device__ __nv_bfloat16  g_xbf[(size_t)MTOT * DIN];   // x quantized, [M][K] bf16
__device__ __nv_bfloat16  g_wbf[(size_t)DOUT * DIN];   // W^T as bf16, [N][K] bf16

// ---------------- helpers ----------------
__device__ __forceinline__ uint32_t smem_u32(const void* p) {
    uint32_t a;
    asm("{ .reg .u64 t; cvta.to.shared.u64 t, %1; cvt.u32.u64 %0, t; }" : "=r"(a) : "l"(p));
    return a;
}

#define CP_ASYNC16(dst, src) \
    asm volatile("cp.async.cg.shared.global [%0], [%1], 16;" :: "r"(dst), "l"(src) : "memory")

#define MBARRIER_INIT(addr, cnt) \
    asm volatile("mbarrier.init.shared.b64 [%0], %1;" :: "r"((uint32_t)(addr)), "r"((uint32_t)(cnt)) : "memory")

#define MBARRIER_ARRIVE(addr) \
    asm volatile("mbarrier.arrive.shared.b64 _, [%0];" :: "r"((uint32_t)(addr)) : "memory")

#define CPASYNC_MBAR_ARRIVE_NOINC(addr) \
    asm volatile("cp.async.mbarrier.arrive.noinc.shared.b64 [%0];" :: "r"((uint32_t)(addr)) : "memory")

#define MBARRIER_WAIT_PARITY(mbar_smem_addr, phase_parity) do { \
    uint32_t _mbar = (uint32_t)(mbar_smem_addr); \
    uint32_t _parity = (uint32_t)(phase_parity); \
    uint32_t _done; \
    asm volatile( \
        "{\n\t.reg .pred p;\n\t" \
        "mbarrier.try_wait.parity.acquire.cta.shared::cta.b64 p, [%1], %2;\n\t" \
        "selp.b32 %0, 1, 0, p;\n\t}" \
        : "=r"(_done) : "r"(_mbar), "r"(_parity) : "memory"); \
    if (!_done) { \
        asm volatile( \
            "{\n\t.reg .pred P1;\n\t" \
            "WAIT_LOOP_%=:\n\t" \
            "mbarrier.try_wait.parity.acquire.cta.shared::cta.b64 P1, [%0], %1, 0x989680;\n\t" \
            "@P1 bra.uni WAIT_DONE_%=;\n\t" \
            "bra.uni WAIT_LOOP_%=;\n\t" \
            "WAIT_DONE_%=:\n\t}" \
            :: "r"(_mbar), "r"(_parity) : "memory"); \
    } \
} while (0)

#define LDSM_X4(r0, r1, r2, r3, addr) \
    asm volatile("ldmatrix.sync.aligned.m8n8.x4.shared.b16 {%0,%1,%2,%3}, [%4];" \
                 : "=r"(r0), "=r"(r1), "=r"(r2), "=r"(r3) : "r"(addr))

__device__ __forceinline__ void hmma_16816(float* c, uint32_t a0, uint32_t a1, uint32_t a2, uint32_t a3,
                                           uint32_t b0, uint32_t b1) {
    asm volatile(
        "mma.sync.aligned.m16n8k16.row.col.f32.bf16.bf16.f32 "
        "{%0,%1,%2,%3}, {%4,%5,%6,%7}, {%8,%9}, {%0,%1,%2,%3};"
        : "+f"(c[0]), "+f"(c[1]), "+f"(c[2]), "+f"(c[3])
        : "r"(a0), "r"(a1), "r"(a2), "r"(a3), "r"(b0), "r"(b1));
}

// ---------------- fused pre-pass: quantize x -> bf16 AND transpose W -> bf16 ----------------
#define QX_BLOCKS 4096
__global__ void prep_kernel(const float* __restrict__ x, const float* __restrict__ w,
                            const float* __restrict__ scale_p) {
    if (blockIdx.x < QX_BLOCKS) {
        const float inv_s = 1.0f / fmaxf(scale_p[0], 1e-8f);
        const int i = blockIdx.x * blockDim.x + threadIdx.x;   // 0 .. M*K/16-1
        const float4* xin = reinterpret_cast<const float4*>(x) + (size_t)i * 4;
        uint32_t bfp[8];
        #pragma unroll
        for (int j = 0; j < 4; j++) {
            float4 v = xin[j];
            float f0 = fminf(fmaxf(rintf(v.x * inv_s), -127.f), 127.f);
            float f1 = fminf(fmaxf(rintf(v.y * inv_s), -127.f), 127.f);
            float f2 = fminf(fmaxf(rintf(v.z * inv_s), -127.f), 127.f);
            float f3 = fminf(fmaxf(rintf(v.w * inv_s), -127.f), 127.f);
            __nv_bfloat162 p0 = __floats2bfloat162_rn(f0, f1);
            __nv_bfloat162 p1 = __floats2bfloat162_rn(f2, f3);
            bfp[2 * j]     = *reinterpret_cast<uint32_t*>(&p0);
            bfp[2 * j + 1] = *reinterpret_cast<uint32_t*>(&p1);
        }
        uint4* bo = reinterpret_cast<uint4*>(g_xbf) + (size_t)i * 2;
        bo[0] = make_uint4(bfp[0], bfp[1], bfp[2], bfp[3]);
        bo[1] = make_uint4(bfp[4], bfp[5], bfp[6], bfp[7]);
    } else {
        __shared__ float t[128][33];     // [k][n]
        const int bid = blockIdx.x - QX_BLOCKS;        // 0..1023
        const int bx = (bid & 63) * 32;                // n tile
        const int by = (bid >> 6) * 128;               // k tile
        const int tx = threadIdx.x & 31;
        const int ty = threadIdx.x >> 5;               // 0..7
        #pragma unroll
        for (int i = ty; i < 128; i += 8)
            t[i][tx] = w[(size_t)(by + i) * DOUT + bx + tx];   // coalesced reads
        __syncthreads();
        #pragma unroll
        for (int r = 0; r < 4; r++) {
            const int n = ty + r * 8;
            __nv_bfloat162 p0 = __floats2bfloat162_rn(t[tx * 4 + 0][n], t[tx * 4 + 1][n]);
            __nv_bfloat162 p1 = __floats2bfloat162_rn(t[tx * 4 + 2][n], t[tx * 4 + 3][n]);
            uint2 bo;
            bo.x = *reinterpret_cast<uint32_t*>(&p0);
            bo.y = *reinterpret_cast<uint32_t*>(&p1);
            *reinterpret_cast<uint2*>(&g_wbf[(size_t)(bx + n) * DIN + by + tx * 4]) = bo;
        }
    }
}

// ---------------- GEMM: 128x64x128 chunks (256B rows), warp 32x32, occ 2 no-spill, mbarrier ----------------
#define BM 128
#define BN 64
#define BK 128                               // bf16 elements = 256 bytes per row-chunk
#define STAGES 2
#define NTHREADS 256
#define NCHUNKS (DIN / BK)                   // 16

#define MBAR_R(s)  (smem_base + (s) * 8)
#define MBAR_D(s)  (smem_base + 32 + (s) * 8)
#define STAGE0_OFF 1024
#define A_STAGE   (BM * 256)                 // 32768
#define B_STAGE   (BN * 256)                 // 16384
#define STAGE_BYTES (A_STAGE + B_STAGE)      // 49152
#define SMEM_TOTAL (STAGE0_OFF + STAGES * STAGE_BYTES)  // 99328

__global__ void __launch_bounds__(NTHREADS, 2) gemm_bf16_kernel(const float* __restrict__ bias,
                                                                float* __restrict__ out) {
    extern __shared__ __align__(1024) char smem[];
    const uint32_t smem_base = smem_u32(smem);
    const int tid  = threadIdx.x;
    const int wid  = tid >> 5;
    const int lane = tid & 31;
    const int wm   = wid >> 1;        // 0..3 : 32-row M block
    const int wn   = wid & 1;         // 0..1 : 32-col N block
    const int g    = lane >> 2;
    const int tg   = lane & 3;

    if (tid == 0) {
        #pragma unroll
        for (int s = 0; s < STAGES; s++) {
            MBARRIER_INIT(MBAR_R(s), NTHREADS);
            MBARRIER_INIT(MBAR_D(s), NTHREADS);
        }
    }
    __syncthreads();

    const __nv_bfloat16* Arow = g_xbf + (size_t)blockIdx.y * BM * DIN;
    const __nv_bfloat16* Brow = g_wbf + (size_t)blockIdx.x * BN * DIN;

    // 192 rows x 16 vecs(16B) = 3072 vecs / 256 thr = 12 each
    // 256B row = two 128B swizzle atoms: phys_vec = (cc&8) | ((cc&7)^(r&7))
    auto load_stage = [&](int stage, int chunk) {
        const int k0 = chunk * BK;
        const uint32_t base = smem_base + STAGE0_OFF + stage * STAGE_BYTES;
        #pragma unroll
        for (int j = 0; j < 12; j++) {
            const int v  = tid + j * 256;
            const int r  = v >> 4;
            const int cc = v & 15;
            const uint32_t phys = (uint32_t)(((cc & 8) | ((cc & 7) ^ (r & 7))) << 4);
            if (r < BM) {
                CP_ASYNC16(base + (uint32_t)r * 256 + phys,
                           reinterpret_cast<const char*>(Arow + (size_t)r * DIN + k0) + cc * 16);
            } else {
                const int r2 = r - BM;
                CP_ASYNC16(base + A_STAGE + (uint32_t)r2 * 256 + phys,
                           reinterpret_cast<const char*>(Brow + (size_t)r2 * DIN + k0) + cc * 16);
            }
        }
    };

    float acc[2][4][4];
    #pragma unroll
    for (int mi = 0; mi < 2; mi++)
        #pragma unroll
        for (int ni = 0; ni < 4; ni++)
            #pragma unroll
            for (int q = 0; q < 4; q++) acc[mi][ni][q] = 0.f;

    // prologue: issue chunk 0
    load_stage(0, 0);
    CPASYNC_MBAR_ARRIVE_NOINC(MBAR_D(0));

    // ---- base LDSM addresses (ks=0); addr(ks) = addr(0) ^ (ks<<5), ks in 0..7 ----
    // cc = col0 + 2*ks; col0 bit4, ks bits 5..7 of the offset; swizzle bits 4..6
    // compose via XOR (verified disjoint/bijective), no carries into row*256.
    const int aRowL = wm * 32 + (lane & 15);
    const int aColL = lane >> 4;                                  // 0/1
    const int bRowL = wn * 32 + (lane & 7) + ((lane >> 4) << 3);
    const int bColL = (lane & 8) ? 1 : 0;

    uint32_t aoff[2], boff[2];
    #pragma unroll
    for (int mi = 0; mi < 2; mi++) {
        const int r = aRowL + mi * 16;
        aoff[mi] = (uint32_t)r * 256 + (uint32_t)((aColL ^ (r & 7)) << 4);
    }
    #pragma unroll
    for (int np = 0; np < 2; np++) {
        const int r = bRowL + np * 16;
        boff[np] = (uint32_t)A_STAGE + (uint32_t)r * 256 + (uint32_t)((bColL ^ (r & 7)) << 4);
    }

    for (int c = 0; c < NCHUNKS; c++) {
        // ---- producer: issue loads for chunk c+1 ----
        const int cc = c + 1;
        if (cc < NCHUNKS) {
            const int sI = cc & 1;
            if (cc >= STAGES) MBARRIER_WAIT_PARITY(MBAR_R(sI), ((cc - STAGES) / STAGES) & 1);
            load_stage(sI, cc);
            CPASYNC_MBAR_ARRIVE_NOINC(MBAR_D(sI));
        }

        // ---- consumer: wait data for chunk c ----
        const int sC = c & 1;
        MBARRIER_WAIT_PARITY(MBAR_D(sC), (c / STAGES) & 1);

        const uint32_t sBase = smem_base + STAGE0_OFF + sC * STAGE_BYTES;

        #pragma unroll
        for (int ks = 0; ks < 8; ks++) {
            const uint32_t kx = (uint32_t)ks << 5;
            uint32_t a[2][4], b[4][2];
            #pragma unroll
            for (int mi = 0; mi < 2; mi++)
                LDSM_X4(a[mi][0], a[mi][1], a[mi][2], a[mi][3], sBase + (aoff[mi] ^ kx));
            #pragma unroll
            for (int np = 0; np < 2; np++)
                LDSM_X4(b[2 * np][0], b[2 * np][1], b[2 * np + 1][0], b[2 * np + 1][1],
                        sBase + (boff[np] ^ kx));
            if (ks == 7) MBARRIER_ARRIVE(MBAR_R(sC));   // all smem reads of this chunk issued
            #pragma unroll
            for (int mi = 0; mi < 2; mi++)
                #pragma unroll
                for (int ni = 0; ni < 4; ni++)
                    hmma_16816(acc[mi][ni], a[mi][0], a[mi][1], a[mi][2], a[mi][3],
                               b[ni][0], b[ni][1]);
        }
    }

    // -------- epilogue: + bias, float2 stores --------
    const int gm0 = blockIdx.y * BM + wm * 32;
    const int gn0 = blockIdx.x * BN + wn * 32;
    #pragma unroll
    for (int ni = 0; ni < 4; ni++) {
        const int col = gn0 + ni * 8 + tg * 2;
        const float2 bb = *reinterpret_cast<const float2*>(bias + col);
        #pragma unroll
        for (int mi = 0; mi < 2; mi++) {
            const int row0 = gm0 + mi * 16 + g;
            float2 o0, o1;
            o0.x = acc[mi][ni][0] + bb.x;
            o0.y = acc[mi][ni][1] + bb.y;
            o1.x = acc[mi][ni][2] + bb.x;
            o1.y = acc[mi][ni][3] + bb.y;
            *reinterpret_cast<float2*>(out + (size_t)row0 * DOUT + col)       = o0;
            *reinterpret_cast<float2*>(out + (size_t)(row0 + 8) * DOUT + col) = o1;
        }
    }
}

// ---------------- launch ----------------
extern "C" void kernel_launch(void* const* d_in, const int* in_sizes, int n_in,
                              void* d_out, int out_size) {
    const float* x    = (const float*)d_in[0];   // [4,2048,2048] fp32
    const float* w    = (const float*)d_in[1];   // [2048,2048] fp32
    const float* xs   = (const float*)d_in[2];   // scalar fp32
    const float* bias = (const float*)d_in[3];   // [2048] fp32
    float* out = (float*)d_out;

    prep_kernel<<<QX_BLOCKS + 1024, 256>>>(x, w, xs);

    static int configured = 0;
    if (!configured) {
        cudaFuncSetAttribute(gemm_bf16_kernel, cudaFuncAttributeMaxDynamicSharedMemorySize, SMEM_TOTAL);
        configured = 1;
    }
    gemm_bf16_kernel<<<dim3(DOUT / BN, MTOT / BM), NTHREADS, SMEM_TOTAL>>>(bias, out);
}

// round 15
// speedup vs baseline: 1.0750x; 1.0750x over previous
#include <cuda_runtime.h>
#include <cuda_bf16.h>
#include <cstdint>

#define DIN   2048
#define DOUT  2048
#define MTOT  8192

// ---------------- scratch (static device globals; no allocation) ----------------
__device__ __nv_bfloat16  g_xbf[(size_t)MTOT * DIN];   // x quantized, [M][K] bf16
__device__ __nv_bfloat16  g_wbf[(size_t)DOUT * DIN];   // W^T as bf16, [N][K] bf16

// ---------------- helpers ----------------
__device__ __forceinline__ uint32_t smem_u32(const void* p) {
    uint32_t a;
    asm("{ .reg .u64 t; cvta.to.shared.u64 t, %1; cvt.u32.u64 %0, t; }" : "=r"(a) : "l"(p));
    return a;
}

#define CP_ASYNC16(dst, src) \
    asm volatile("cp.async.cg.shared.global [%0], [%1], 16;" :: "r"(dst), "l"(src) : "memory")

#define MBARRIER_INIT(addr, cnt) \
    asm volatile("mbarrier.init.shared.b64 [%0], %1;" :: "r"((uint32_t)(addr)), "r"((uint32_t)(cnt)) : "memory")

#define MBARRIER_ARRIVE(addr) \
    asm volatile("mbarrier.arrive.shared.b64 _, [%0];" :: "r"((uint32_t)(addr)) : "memory")

#define CPASYNC_MBAR_ARRIVE_NOINC(addr) \
    asm volatile("cp.async.mbarrier.arrive.noinc.shared.b64 [%0];" :: "r"((uint32_t)(addr)) : "memory")

#define MBARRIER_WAIT_PARITY(mbar_smem_addr, phase_parity) do { \
    uint32_t _mbar = (uint32_t)(mbar_smem_addr); \
    uint32_t _parity = (uint32_t)(phase_parity); \
    uint32_t _done; \
    asm volatile( \
        "{\n\t.reg .pred p;\n\t" \
        "mbarrier.try_wait.parity.acquire.cta.shared::cta.b64 p, [%1], %2;\n\t" \
        "selp.b32 %0, 1, 0, p;\n\t}" \
        : "=r"(_done) : "r"(_mbar), "r"(_parity) : "memory"); \
    if (!_done) { \
        asm volatile( \
            "{\n\t.reg .pred P1;\n\t" \
            "WAIT_LOOP_%=:\n\t" \
            "mbarrier.try_wait.parity.acquire.cta.shared::cta.b64 P1, [%0], %1, 0x989680;\n\t" \
            "@P1 bra.uni WAIT_DONE_%=;\n\t" \
            "bra.uni WAIT_LOOP_%=;\n\t" \
            "WAIT_DONE_%=:\n\t}" \
            :: "r"(_mbar), "r"(_parity) : "memory"); \
    } \
} while (0)

#define LDSM_X4(r0, r1, r2, r3, addr) \
    asm volatile("ldmatrix.sync.aligned.m8n8.x4.shared.b16 {%0,%1,%2,%3}, [%4];" \
                 : "=r"(r0), "=r"(r1), "=r"(r2), "=r"(r3) : "r"(addr))

__device__ __forceinline__ void hmma_16816(float* c, uint32_t a0, uint32_t a1, uint32_t a2, uint32_t a3,
                                           uint32_t b0, uint32_t b1) {
    asm volatile(
        "mma.sync.aligned.m16n8k16.row.col.f32.bf16.bf16.f32 "
        "{%0,%1,%2,%3}, {%4,%5,%6,%7}, {%8,%9}, {%0,%1,%2,%3};"
        : "+f"(c[0]), "+f"(c[1]), "+f"(c[2]), "+f"(c[3])
        : "r"(a0), "r"(a1), "r"(a2), "r"(a3), "r"(b0), "r"(b1));
}

// ---------------- fused pre-pass: quantize x -> bf16 AND transpose W -> bf16 (R10 form) ----------------
#define QX_BLOCKS 4096
__global__ void prep_kernel(const float* __restrict__ x, const float* __restrict__ w,
                            const float* __restrict__ scale_p) {
    if (blockIdx.x < QX_BLOCKS) {
        const float inv_s = 1.0f / fmaxf(scale_p[0], 1e-8f);
        const int i = blockIdx.x * blockDim.x + threadIdx.x;   // 0 .. M*K/16-1
        const float4* xin = reinterpret_cast<const float4*>(x) + (size_t)i * 4;
        uint32_t bfp[8];
        #pragma unroll
        for (int j = 0; j < 4; j++) {
            float4 v = xin[j];
            float f0 = fminf(fmaxf(rintf(v.x * inv_s), -127.f), 127.f);
            float f1 = fminf(fmaxf(rintf(v.y * inv_s), -127.f), 127.f);
            float f2 = fminf(fmaxf(rintf(v.z * inv_s), -127.f), 127.f);
            float f3 = fminf(fmaxf(rintf(v.w * inv_s), -127.f), 127.f);
            __nv_bfloat162 p0 = __floats2bfloat162_rn(f0, f1);
            __nv_bfloat162 p1 = __floats2bfloat162_rn(f2, f3);
            bfp[2 * j]     = *reinterpret_cast<uint32_t*>(&p0);
            bfp[2 * j + 1] = *reinterpret_cast<uint32_t*>(&p1);
        }
        uint4* bo = reinterpret_cast<uint4*>(g_xbf) + (size_t)i * 2;
        bo[0] = make_uint4(bfp[0], bfp[1], bfp[2], bfp[3]);
        bo[1] = make_uint4(bfp[4], bfp[5], bfp[6], bfp[7]);
    } else {
        __shared__ float t[128][33];     // [k][n]
        const int bid = blockIdx.x - QX_BLOCKS;        // 0..1023
        const int bx = (bid & 63) * 32;                // n tile
        const int by = (bid >> 6) * 128;               // k tile
        const int tx = threadIdx.x & 31;
        const int ty = threadIdx.x >> 5;               // 0..7
        #pragma unroll
        for (int i = ty; i < 128; i += 8)
            t[i][tx] = w[(size_t)(by + i) * DOUT + bx + tx];   // coalesced reads
        __syncthreads();
        #pragma unroll
        for (int r = 0; r < 4; r++) {
            const int n = ty + r * 8;
            __nv_bfloat162 p0 = __floats2bfloat162_rn(t[tx * 4 + 0][n], t[tx * 4 + 1][n]);
            __nv_bfloat162 p1 = __floats2bfloat162_rn(t[tx * 4 + 2][n], t[tx * 4 + 3][n]);
            uint2 bo;
            bo.x = *reinterpret_cast<uint32_t*>(&p0);
            bo.y = *reinterpret_cast<uint32_t*>(&p1);
            *reinterpret_cast<uint2*>(&g_wbf[(size_t)(bx + n) * DIN + by + tx * 4]) = bo;
        }
    }
}

// ---------------- GEMM: 128x128x64, swizzled, warp 32x64, occ 2, mbarrier pipeline (R10 + XOR addr) ----------------
#define BM 128
#define BN 128
#define BK 64
#define STAGES 3
#define NTHREADS 256
#define NCHUNKS (DIN / BK)                   // 32

#define MBAR_R(s)  (smem_base + (s) * 8)
#define MBAR_D(s)  (smem_base + 32 + (s) * 8)
#define STAGE0_OFF 1024
#define A_STAGE   (BM * 128)                 // 16384
#define B_STAGE   (BN * 128)                 // 16384
#define STAGE_BYTES (A_STAGE + B_STAGE)      // 32768
#define SMEM_TOTAL (STAGE0_OFF + STAGES * STAGE_BYTES)  // 99328

__global__ void __launch_bounds__(NTHREADS, 2) gemm_bf16_kernel(const float* __restrict__ bias,
                                                                float* __restrict__ out) {
    extern __shared__ __align__(1024) char smem[];
    const uint32_t smem_base = smem_u32(smem);
    const int tid  = threadIdx.x;
    const int wid  = tid >> 5;
    const int lane = tid & 31;
    const int wm   = wid >> 1;        // 0..3 : 32-row M block
    const int wn   = wid & 1;         // 0..1 : 64-col N block
    const int g    = lane >> 2;
    const int tg   = lane & 3;

    if (tid == 0) {
        #pragma unroll
        for (int s = 0; s < STAGES; s++) {
            MBARRIER_INIT(MBAR_R(s), NTHREADS);
            MBARRIER_INIT(MBAR_D(s), NTHREADS);
        }
    }
    __syncthreads();

    const __nv_bfloat16* Arow = g_xbf + (size_t)blockIdx.y * BM * DIN;
    const __nv_bfloat16* Brow = g_wbf + (size_t)blockIdx.x * BN * DIN;

    auto load_stage = [&](int stage, int chunk) {
        const int k0 = chunk * BK;
        const uint32_t base = smem_base + STAGE0_OFF + stage * STAGE_BYTES;
        #pragma unroll
        for (int j = 0; j < 8; j++) {
            const int v  = tid + j * 256;
            const int r  = v >> 3;
            const int cc = v & 7;
            const uint32_t dst_off = (uint32_t)(r & 127) * 128 + ((cc ^ (r & 7)) << 4);
            if (r < BM) {
                CP_ASYNC16(base + dst_off,
                           reinterpret_cast<const char*>(Arow + (size_t)r * DIN + k0) + cc * 16);
            } else {
                CP_ASYNC16(base + A_STAGE + dst_off,
                           reinterpret_cast<const char*>(Brow + (size_t)(r - BM) * DIN + k0) + cc * 16);
            }
        }
    };

    float acc[2][8][4];
    #pragma unroll
    for (int mi = 0; mi < 2; mi++)
        #pragma unroll
        for (int ni = 0; ni < 8; ni++)
            #pragma unroll
            for (int q = 0; q < 4; q++) acc[mi][ni][q] = 0.f;

    // prologue: issue chunks 0 and 1
    load_stage(0, 0);
    CPASYNC_MBAR_ARRIVE_NOINC(MBAR_D(0));
    load_stage(1, 1);
    CPASYNC_MBAR_ARRIVE_NOINC(MBAR_D(1));

    // ---- 6 base LDSM addresses (ks=0); addr(ks) = addr(0) ^ (ks<<5) ----
    // valid: col0 occupies bit 4 group {0,1}<<4, ks*2 occupies bits 5-6, swizzle
    // XOR acts on bits 4-6 bijectively; no carries into row*128 bits. rel_err=0
    // verified for this mapping in R13/R14 runs.
    const int aRowL = wm * 32 + (lane & 15);
    const int aColL = lane >> 4;
    const int bRowL = wn * 64 + (lane & 7) + ((lane >> 4) << 3);
    const int bColL = (lane & 8) ? 1 : 0;

    uint32_t aoff[2], boff[4];
    #pragma unroll
    for (int mi = 0; mi < 2; mi++) {
        const int r = aRowL + mi * 16;
        aoff[mi] = (uint32_t)r * 128 + (uint32_t)((aColL ^ (r & 7)) << 4);
    }
    #pragma unroll
    for (int np = 0; np < 4; np++) {
        const int r = bRowL + np * 16;
        boff[np] = (uint32_t)A_STAGE + (uint32_t)r * 128 + (uint32_t)((bColL ^ (r & 7)) << 4);
    }

    for (int c = 0; c < NCHUNKS; c++) {
        // ---- producer: issue loads for chunk c+2 ----
        const int cc = c + 2;
        if (cc < NCHUNKS) {
            const int sI = cc % STAGES;
            if (cc >= STAGES) MBARRIER_WAIT_PARITY(MBAR_R(sI), ((cc - STAGES) / STAGES) & 1);
            load_stage(sI, cc);
            CPASYNC_MBAR_ARRIVE_NOINC(MBAR_D(sI));
        }

        // ---- consumer: wait data for chunk c ----
        const int sC = c % STAGES;
        MBARRIER_WAIT_PARITY(MBAR_D(sC), (c / STAGES) & 1);

        const uint32_t sBase = smem_base + STAGE0_OFF + sC * STAGE_BYTES;

        // whole-chunk fragment buffering (R10 schedule), XOR addressing
        uint32_t a[4][2][4], b[4][8][2];
        #pragma unroll
        for (int ks = 0; ks < 4; ks++) {
            const uint32_t kx = (uint32_t)ks << 5;
            #pragma unroll
            for (int mi = 0; mi < 2; mi++)
                LDSM_X4(a[ks][mi][0], a[ks][mi][1], a[ks][mi][2], a[ks][mi][3],
                        sBase + (aoff[mi] ^ kx));
            #pragma unroll
            for (int np = 0; np < 4; np++)
                LDSM_X4(b[ks][2 * np][0], b[ks][2 * np][1], b[ks][2 * np + 1][0], b[ks][2 * np + 1][1],
                        sBase + (boff[np] ^ kx));
            if (ks == 3) MBARRIER_ARRIVE(MBAR_R(sC));   // all smem reads of this chunk issued
            #pragma unroll
            for (int mi = 0; mi < 2; mi++)
                #pragma unroll
                for (int ni = 0; ni < 8; ni++)
                    hmma_16816(acc[mi][ni], a[ks][mi][0], a[ks][mi][1], a[ks][mi][2], a[ks][mi][3],
                               b[ks][ni][0], b[ks][ni][1]);
        }
    }

    // -------- epilogue: + bias, float2 stores --------
    const int gm0 = blockIdx.y * BM + wm * 32;
    const int gn0 = blockIdx.x * BN + wn * 64;
    #pragma unroll
    for (int ni = 0; ni < 8; ni++) {
        const int col = gn0 + ni * 8 + tg * 2;
        const float2 bb = *reinterpret_cast<const float2*>(bias + col);
        #pragma unroll
        for (int mi = 0; mi < 2; mi++) {
            const int row0 = gm0 + mi * 16 + g;
            float2 o0, o1;
            o0.x = acc[mi][ni][0] + bb.x;
            o0.y = acc[mi][ni][1] + bb.y;
            o1.x = acc[mi][ni][2] + bb.x;
            o1.y = acc[mi][ni][3] + bb.y;
            *reinterpret_cast<float2*>(out + (size_t)row0 * DOUT + col)       = o0;
            *reinterpret_cast<float2*>(out + (size_t)(row0 + 8) * DOUT + col) = o1;
        }
    }
}

// ---------------- launch ----------------
extern "C" void kernel_launch(void* const* d_in, const int* in_sizes, int n_in,
                              void* d_out, int out_size) {
    const float* x    = (const float*)d_in[0];   // [4,2048,2048] fp32
    const float* w    = (const float*)d_in[1];   // [2048,2048] fp32
    const float* xs   = (const float*)d_in[2];   // scalar fp32
    const float* bias = (const float*)d_in[3];   // [2048] fp32
    float* out = (float*)d_out;

    prep_kernel<<<QX_BLOCKS + 1024, 256>>>(x, w, xs);

    static int configured = 0;
    if (!configured) {
        cudaFuncSetAttribute(gemm_bf16_kernel, cudaFuncAttributeMaxDynamicSharedMemorySize, SMEM_TOTAL);
        configured = 1;
    }
    gemm_bf16_kernel<<<dim3(DOUT / BN, MTOT / BM), NTHREADS, SMEM_TOTAL>>>(bias, out);
}

// round 16
// speedup vs baseline: 1.0972x; 1.0207x over previous
#include <cuda_runtime.h>
#include <cuda_bf16.h>
#include <cstdint>

#define DIN   2048
#define DOUT  2048
#define MTOT  8192

// ---------------- scratch (static device globals; no allocation) ----------------
__device__ __nv_bfloat16  g_xbf[(size_t)MTOT * DIN];   // x quantized, [M][K] bf16
__device__ __nv_bfloat16  g_wbf[(size_t)DOUT * DIN];   // W^T as bf16, [N][K] bf16

// ---------------- helpers ----------------
__device__ __forceinline__ uint32_t smem_u32(const void* p) {
    uint32_t a;
    asm("{ .reg .u64 t; cvta.to.shared.u64 t, %1; cvt.u32.u64 %0, t; }" : "=r"(a) : "l"(p));
    return a;
}

#define CP_ASYNC16(dst, src) \
    asm volatile("cp.async.cg.shared.global [%0], [%1], 16;" :: "r"(dst), "l"(src) : "memory")

#define MBARRIER_INIT(addr, cnt) \
    asm volatile("mbarrier.init.shared.b64 [%0], %1;" :: "r"((uint32_t)(addr)), "r"((uint32_t)(cnt)) : "memory")

#define MBARRIER_ARRIVE(addr) \
    asm volatile("mbarrier.arrive.shared.b64 _, [%0];" :: "r"((uint32_t)(addr)) : "memory")

#define CPASYNC_MBAR_ARRIVE_NOINC(addr) \
    asm volatile("cp.async.mbarrier.arrive.noinc.shared.b64 [%0];" :: "r"((uint32_t)(addr)) : "memory")

#define MBARRIER_WAIT_PARITY(mbar_smem_addr, phase_parity) do { \
    uint32_t _mbar = (uint32_t)(mbar_smem_addr); \
    uint32_t _parity = (uint32_t)(phase_parity); \
    uint32_t _done; \
    asm volatile( \
        "{\n\t.reg .pred p;\n\t" \
        "mbarrier.try_wait.parity.acquire.cta.shared::cta.b64 p, [%1], %2;\n\t" \
        "selp.b32 %0, 1, 0, p;\n\t}" \
        : "=r"(_done) : "r"(_mbar), "r"(_parity) : "memory"); \
    if (!_done) { \
        asm volatile( \
            "{\n\t.reg .pred P1;\n\t" \
            "WAIT_LOOP_%=:\n\t" \
            "mbarrier.try_wait.parity.acquire.cta.shared::cta.b64 P1, [%0], %1, 0x989680;\n\t" \
            "@P1 bra.uni WAIT_DONE_%=;\n\t" \
            "bra.uni WAIT_LOOP_%=;\n\t" \
            "WAIT_DONE_%=:\n\t}" \
            :: "r"(_mbar), "r"(_parity) : "memory"); \
    } \
} while (0)

#define LDSM_X4(r0, r1, r2, r3, addr) \
    asm volatile("ldmatrix.sync.aligned.m8n8.x4.shared.b16 {%0,%1,%2,%3}, [%4];" \
                 : "=r"(r0), "=r"(r1), "=r"(r2), "=r"(r3) : "r"(addr))

__device__ __forceinline__ void hmma_16816(float* c, uint32_t a0, uint32_t a1, uint32_t a2, uint32_t a3,
                                           uint32_t b0, uint32_t b1) {
    asm volatile(
        "mma.sync.aligned.m16n8k16.row.col.f32.bf16.bf16.f32 "
        "{%0,%1,%2,%3}, {%4,%5,%6,%7}, {%8,%9}, {%0,%1,%2,%3};"
        : "+f"(c[0]), "+f"(c[1]), "+f"(c[2]), "+f"(c[3])
        : "r"(a0), "r"(a1), "r"(a2), "r"(a3), "r"(b0), "r"(b1));
}

// ---------------- fused pre-pass: W-transpose blocks FIRST, then x-quant blocks ----------------
// W blocks are latency-bound (smem transpose + syncs); scheduling them first overlaps
// them with the x streaming blocks instead of leaving them as a low-BW tail wave.
#define W_BLOCKS  1024
#define QX_BLOCKS 4096
__global__ void prep_kernel(const float* __restrict__ x, const float* __restrict__ w,
                            const float* __restrict__ scale_p) {
    if (blockIdx.x < W_BLOCKS) {
        __shared__ float t[128][33];     // [k][n]
        const int bid = blockIdx.x;                    // 0..1023
        const int bx = (bid & 63) * 32;                // n tile
        const int by = (bid >> 6) * 128;               // k tile
        const int tx = threadIdx.x & 31;
        const int ty = threadIdx.x >> 5;               // 0..7
        #pragma unroll
        for (int i = ty; i < 128; i += 8)
            t[i][tx] = w[(size_t)(by + i) * DOUT + bx + tx];   // coalesced reads
        __syncthreads();
        #pragma unroll
        for (int r = 0; r < 4; r++) {
            const int n = ty + r * 8;
            __nv_bfloat162 p0 = __floats2bfloat162_rn(t[tx * 4 + 0][n], t[tx * 4 + 1][n]);
            __nv_bfloat162 p1 = __floats2bfloat162_rn(t[tx * 4 + 2][n], t[tx * 4 + 3][n]);
            uint2 bo;
            bo.x = *reinterpret_cast<uint32_t*>(&p0);
            bo.y = *reinterpret_cast<uint32_t*>(&p1);
            *reinterpret_cast<uint2*>(&g_wbf[(size_t)(bx + n) * DIN + by + tx * 4]) = bo;
        }
    } else {
        const float inv_s = 1.0f / fmaxf(scale_p[0], 1e-8f);
        const int i = (blockIdx.x - W_BLOCKS) * blockDim.x + threadIdx.x;  // 0 .. M*K/16-1
        const float4* xin = reinterpret_cast<const float4*>(x) + (size_t)i * 4;
        uint32_t bfp[8];
        #pragma unroll
        for (int j = 0; j < 4; j++) {
            float4 v = xin[j];
            float f0 = fminf(fmaxf(rintf(v.x * inv_s), -127.f), 127.f);
            float f1 = fminf(fmaxf(rintf(v.y * inv_s), -127.f), 127.f);
            float f2 = fminf(fmaxf(rintf(v.z * inv_s), -127.f), 127.f);
            float f3 = fminf(fmaxf(rintf(v.w * inv_s), -127.f), 127.f);
            __nv_bfloat162 p0 = __floats2bfloat162_rn(f0, f1);
            __nv_bfloat162 p1 = __floats2bfloat162_rn(f2, f3);
            bfp[2 * j]     = *reinterpret_cast<uint32_t*>(&p0);
            bfp[2 * j + 1] = *reinterpret_cast<uint32_t*>(&p1);
        }
        uint4* bo = reinterpret_cast<uint4*>(g_xbf) + (size_t)i * 2;
        bo[0] = make_uint4(bfp[0], bfp[1], bfp[2], bfp[3]);
        bo[1] = make_uint4(bfp[4], bfp[5], bfp[6], bfp[7]);
    }
}

// ---------------- GEMM: 128x128x64, swizzled, warp 32x64, occ 2, mbarrier pipeline (R10 exact) ----------------
#define BM 128
#define BN 128
#define BK 64
#define STAGES 3
#define NTHREADS 256
#define NCHUNKS (DIN / BK)                   // 32

#define MBAR_R(s)  (smem_base + (s) * 8)
#define MBAR_D(s)  (smem_base + 32 + (s) * 8)
#define STAGE0_OFF 1024
#define A_STAGE   (BM * 128)                 // 16384
#define B_STAGE   (BN * 128)                 // 16384
#define STAGE_BYTES (A_STAGE + B_STAGE)      // 32768
#define SMEM_TOTAL (STAGE0_OFF + STAGES * STAGE_BYTES)  // 99328

__global__ void __launch_bounds__(NTHREADS, 2) gemm_bf16_kernel(const float* __restrict__ bias,
                                                                float* __restrict__ out) {
    extern __shared__ __align__(1024) char smem[];
    const uint32_t smem_base = smem_u32(smem);
    const int tid  = threadIdx.x;
    const int wid  = tid >> 5;
    const int lane = tid & 31;
    const int wm   = wid >> 1;        // 0..3 : 32-row M block
    const int wn   = wid & 1;         // 0..1 : 64-col N block
    const int g    = lane >> 2;
    const int tg   = lane & 3;

    if (tid == 0) {
        #pragma unroll
        for (int s = 0; s < STAGES; s++) {
            MBARRIER_INIT(MBAR_R(s), NTHREADS);
            MBARRIER_INIT(MBAR_D(s), NTHREADS);
        }
    }
    __syncthreads();

    const __nv_bfloat16* Arow = g_xbf + (size_t)blockIdx.y * BM * DIN;
    const __nv_bfloat16* Brow = g_wbf + (size_t)blockIdx.x * BN * DIN;

    auto load_stage = [&](int stage, int chunk) {
        const int k0 = chunk * BK;
        const uint32_t base = smem_base + STAGE0_OFF + stage * STAGE_BYTES;
        #pragma unroll
        for (int j = 0; j < 8; j++) {
            const int v  = tid + j * 256;
            const int r  = v >> 3;
            const int cc = v & 7;
            const uint32_t dst_off = (uint32_t)(r & 127) * 128 + ((cc ^ (r & 7)) << 4);
            if (r < BM) {
                CP_ASYNC16(base + dst_off,
                           reinterpret_cast<const char*>(Arow + (size_t)r * DIN + k0) + cc * 16);
            } else {
                CP_ASYNC16(base + A_STAGE + dst_off,
                           reinterpret_cast<const char*>(Brow + (size_t)(r - BM) * DIN + k0) + cc * 16);
            }
        }
    };

    float acc[2][8][4];
    #pragma unroll
    for (int mi = 0; mi < 2; mi++)
        #pragma unroll
        for (int ni = 0; ni < 8; ni++)
            #pragma unroll
            for (int q = 0; q < 4; q++) acc[mi][ni][q] = 0.f;

    // prologue: issue chunks 0 and 1
    load_stage(0, 0);
    CPASYNC_MBAR_ARRIVE_NOINC(MBAR_D(0));
    load_stage(1, 1);
    CPASYNC_MBAR_ARRIVE_NOINC(MBAR_D(1));

    // per-lane row/col components for swizzled LDSM addressing (validated R8/R10)
    const int aRowL = wm * 32 + (lane & 15);
    const int aColL = lane >> 4;
    const int bRowL = wn * 64 + (lane & 7) + ((lane >> 4) << 3);
    const int bColL = (lane & 8) ? 1 : 0;

    for (int c = 0; c < NCHUNKS; c++) {
        // ---- producer: issue loads for chunk c+2 ----
        const int cc = c + 2;
        if (cc < NCHUNKS) {
            const int sI = cc % STAGES;
            if (cc >= STAGES) MBARRIER_WAIT_PARITY(MBAR_R(sI), ((cc - STAGES) / STAGES) & 1);
            load_stage(sI, cc);
            CPASYNC_MBAR_ARRIVE_NOINC(MBAR_D(sI));
        }

        // ---- consumer: wait data for chunk c ----
        const int sC = c % STAGES;
        MBARRIER_WAIT_PARITY(MBAR_D(sC), (c / STAGES) & 1);

        const uint32_t sA = smem_base + STAGE0_OFF + sC * STAGE_BYTES;
        const uint32_t sB = sA + A_STAGE;

        // load ALL fragments for the chunk, then signal reads-done, then HMMA
        uint32_t a[4][2][4], b[4][8][2];
        #pragma unroll
        for (int ks = 0; ks < 4; ks++) {
            #pragma unroll
            for (int mi = 0; mi < 2; mi++) {
                const int r = aRowL + mi * 16;
                const int ccol = (aColL + ks * 2) ^ (r & 7);
                LDSM_X4(a[ks][mi][0], a[ks][mi][1], a[ks][mi][2], a[ks][mi][3],
                        sA + (uint32_t)r * 128 + (ccol << 4));
            }
            #pragma unroll
            for (int np = 0; np < 4; np++) {
                const int r = bRowL + np * 16;
                const int ccol = (bColL + ks * 2) ^ (r & 7);
                LDSM_X4(b[ks][2 * np][0], b[ks][2 * np][1], b[ks][2 * np + 1][0], b[ks][2 * np + 1][1],
                        sB + (uint32_t)r * 128 + (ccol << 4));
            }
            if (ks == 3) MBARRIER_ARRIVE(MBAR_R(sC));   // all smem reads of this chunk issued
            #pragma unroll
            for (int mi = 0; mi < 2; mi++)
                #pragma unroll
                for (int ni = 0; ni < 8; ni++)
                    hmma_16816(acc[mi][ni], a[ks][mi][0], a[ks][mi][1], a[ks][mi][2], a[ks][mi][3],
                               b[ks][ni][0], b[ks][ni][1]);
        }
    }

    // -------- epilogue: + bias, float2 stores --------
    const int gm0 = blockIdx.y * BM + wm * 32;
    const int gn0 = blockIdx.x * BN + wn * 64;
    #pragma unroll
    for (int ni = 0; ni < 8; ni++) {
        const int col = gn0 + ni * 8 + tg * 2;
        const float2 bb = *reinterpret_cast<const float2*>(bias + col);
        #pragma unroll
        for (int mi = 0; mi < 2; mi++) {
            const int row0 = gm0 + mi * 16 + g;
            float2 o0, o1;
            o0.x = acc[mi][ni][0] + bb.x;
            o0.y = acc[mi][ni][1] + bb.y;
            o1.x = acc[mi][ni][2] + bb.x;
            o1.y = acc[mi][ni][3] + bb.y;
            *reinterpret_cast<float2*>(out + (size_t)row0 * DOUT + col)       = o0;
            *reinterpret_cast<float2*>(out + (size_t)(row0 + 8) * DOUT + col) = o1;
        }
    }
}

// ---------------- launch ----------------
extern "C" void kernel_launch(void* const* d_in, const int* in_sizes, int n_in,
                              void* d_out, int out_size) {
    const float* x    = (const float*)d_in[0];   // [4,2048,2048] fp32
    const float* w    = (const float*)d_in[1];   // [2048,2048] fp32
    const float* xs   = (const float*)d_in[2];   // scalar fp32
    const float* bias = (const float*)d_in[3];   // [2048] fp32
    float* out = (float*)d_out;

    prep_kernel<<<W_BLOCKS + QX_BLOCKS, 256>>>(x, w, xs);

    static int configured = 0;
    if (!configured) {
        cudaFuncSetAttribute(gemm_bf16_kernel, cudaFuncAttributeMaxDynamicSharedMemorySize, SMEM_TOTAL);
        configured = 1;
    }
    gemm_bf16_kernel<<<dim3(DOUT / BN, MTOT / BM), NTHREADS, SMEM_TOTAL>>>(bias, out);
}

// round 17
// speedup vs baseline: 1.1599x; 1.0571x over previous
#include <cuda_runtime.h>
#include <cuda_bf16.h>
#include <cstdint>

#define DIN   2048
#define DOUT  2048
#define MTOT  8192

// ---------------- scratch (static device globals; no allocation) ----------------
__device__ __nv_bfloat16  g_xbf[(size_t)MTOT * DIN];   // x quantized, [M][K] bf16
__device__ __nv_bfloat16  g_wbf[(size_t)DIN * DOUT];   // W as bf16, native [K][N] layout

// ---------------- helpers ----------------
__device__ __forceinline__ uint32_t smem_u32(const void* p) {
    uint32_t a;
    asm("{ .reg .u64 t; cvta.to.shared.u64 t, %1; cvt.u32.u64 %0, t; }" : "=r"(a) : "l"(p));
    return a;
}

#define CP_ASYNC16(dst, src) \
    asm volatile("cp.async.cg.shared.global [%0], [%1], 16;" :: "r"(dst), "l"(src) : "memory")

#define MBARRIER_INIT(addr, cnt) \
    asm volatile("mbarrier.init.shared.b64 [%0], %1;" :: "r"((uint32_t)(addr)), "r"((uint32_t)(cnt)) : "memory")

#define MBARRIER_ARRIVE(addr) \
    asm volatile("mbarrier.arrive.shared.b64 _, [%0];" :: "r"((uint32_t)(addr)) : "memory")

#define CPASYNC_MBAR_ARRIVE_NOINC(addr) \
    asm volatile("cp.async.mbarrier.arrive.noinc.shared.b64 [%0];" :: "r"((uint32_t)(addr)) : "memory")

#define MBARRIER_WAIT_PARITY(mbar_smem_addr, phase_parity) do { \
    uint32_t _mbar = (uint32_t)(mbar_smem_addr); \
    uint32_t _parity = (uint32_t)(phase_parity); \
    uint32_t _done; \
    asm volatile( \
        "{\n\t.reg .pred p;\n\t" \
        "mbarrier.try_wait.parity.acquire.cta.shared::cta.b64 p, [%1], %2;\n\t" \
        "selp.b32 %0, 1, 0, p;\n\t}" \
        : "=r"(_done) : "r"(_mbar), "r"(_parity) : "memory"); \
    if (!_done) { \
        asm volatile( \
            "{\n\t.reg .pred P1;\n\t" \
            "WAIT_LOOP_%=:\n\t" \
            "mbarrier.try_wait.parity.acquire.cta.shared::cta.b64 P1, [%0], %1, 0x989680;\n\t" \
            "@P1 bra.uni WAIT_DONE_%=;\n\t" \
            "bra.uni WAIT_LOOP_%=;\n\t" \
            "WAIT_DONE_%=:\n\t}" \
            :: "r"(_mbar), "r"(_parity) : "memory"); \
    } \
} while (0)

#define LDSM_X4(r0, r1, r2, r3, addr) \
    asm volatile("ldmatrix.sync.aligned.m8n8.x4.shared.b16 {%0,%1,%2,%3}, [%4];" \
                 : "=r"(r0), "=r"(r1), "=r"(r2), "=r"(r3) : "r"(addr))

#define LDSM_X4_T(r0, r1, r2, r3, addr) \
    asm volatile("ldmatrix.sync.aligned.m8n8.x4.trans.shared.b16 {%0,%1,%2,%3}, [%4];" \
                 : "=r"(r0), "=r"(r1), "=r"(r2), "=r"(r3) : "r"(addr))

__device__ __forceinline__ void hmma_16816(float* c, uint32_t a0, uint32_t a1, uint32_t a2, uint32_t a3,
                                           uint32_t b0, uint32_t b1) {
    asm volatile(
        "mma.sync.aligned.m16n8k16.row.col.f32.bf16.bf16.f32 "
        "{%0,%1,%2,%3}, {%4,%5,%6,%7}, {%8,%9}, {%0,%1,%2,%3};"
        : "+f"(c[0]), "+f"(c[1]), "+f"(c[2]), "+f"(c[3])
        : "r"(a0), "r"(a1), "r"(a2), "r"(a3), "r"(b0), "r"(b1));
}

// ---------------- fused pre-pass: W-convert blocks FIRST (streaming), then x-quant ----------------
#define W_BLOCKS  1024          // 4M W elements / (256 thr * 16 elem)
#define QX_BLOCKS 4096          // 16M x elements / (256 thr * 16 elem)
__global__ void prep_kernel(const float* __restrict__ x, const float* __restrict__ w,
                            const float* __restrict__ scale_p) {
    if (blockIdx.x < W_BLOCKS) {
        // pure streaming fp32 -> bf16 convert, native [K][N] layout preserved
        const int i = blockIdx.x * blockDim.x + threadIdx.x;   // 0 .. K*N/16-1
        const float4* win = reinterpret_cast<const float4*>(w) + (size_t)i * 4;
        uint32_t bfp[8];
        #pragma unroll
        for (int j = 0; j < 4; j++) {
            float4 v = win[j];
            __nv_bfloat162 p0 = __floats2bfloat162_rn(v.x, v.y);
            __nv_bfloat162 p1 = __floats2bfloat162_rn(v.z, v.w);
            bfp[2 * j]     = *reinterpret_cast<uint32_t*>(&p0);
            bfp[2 * j + 1] = *reinterpret_cast<uint32_t*>(&p1);
        }
        uint4* bo = reinterpret_cast<uint4*>(g_wbf) + (size_t)i * 2;
        bo[0] = make_uint4(bfp[0], bfp[1], bfp[2], bfp[3]);
        bo[1] = make_uint4(bfp[4], bfp[5], bfp[6], bfp[7]);
    } else {
        const float inv_s = 1.0f / fmaxf(scale_p[0], 1e-8f);
        const int i = (blockIdx.x - W_BLOCKS) * blockDim.x + threadIdx.x;  // 0 .. M*K/16-1
        const float4* xin = reinterpret_cast<const float4*>(x) + (size_t)i * 4;
        uint32_t bfp[8];
        #pragma unroll
        for (int j = 0; j < 4; j++) {
            float4 v = xin[j];
            float f0 = fminf(fmaxf(rintf(v.x * inv_s), -127.f), 127.f);
            float f1 = fminf(fmaxf(rintf(v.y * inv_s), -127.f), 127.f);
            float f2 = fminf(fmaxf(rintf(v.z * inv_s), -127.f), 127.f);
            float f3 = fminf(fmaxf(rintf(v.w * inv_s), -127.f), 127.f);
            __nv_bfloat162 p0 = __floats2bfloat162_rn(f0, f1);
            __nv_bfloat162 p1 = __floats2bfloat162_rn(f2, f3);
            bfp[2 * j]     = *reinterpret_cast<uint32_t*>(&p0);
            bfp[2 * j + 1] = *reinterpret_cast<uint32_t*>(&p1);
        }
        uint4* bo = reinterpret_cast<uint4*>(g_xbf) + (size_t)i * 2;
        bo[0] = make_uint4(bfp[0], bfp[1], bfp[2], bfp[3]);
        bo[1] = make_uint4(bfp[4], bfp[5], bfp[6], bfp[7]);
    }
}

// ---------------- GEMM: 128x128x64, warp 32x64, occ 2, mbarrier pipeline, B via ldmatrix.trans ----------------
#define BM 128
#define BN 128
#define BK 64
#define STAGES 3
#define NTHREADS 256
#define NCHUNKS (DIN / BK)                   // 32

#define MBAR_R(s)  (smem_base + (s) * 8)
#define MBAR_D(s)  (smem_base + 32 + (s) * 8)
#define STAGE0_OFF 1024
#define A_STAGE   (BM * 128)                 // 16384  (128 m-rows x 128B)
#define B_STAGE   (BK * 256)                 // 16384  (64 k-rows x 256B = 128 n bf16)
#define STAGE_BYTES (A_STAGE + B_STAGE)      // 32768
#define SMEM_TOTAL (STAGE0_OFF + STAGES * STAGE_BYTES)  // 99328

__global__ void __launch_bounds__(NTHREADS, 2) gemm_bf16_kernel(const float* __restrict__ bias,
                                                                float* __restrict__ out) {
    extern __shared__ __align__(1024) char smem[];
    const uint32_t smem_base = smem_u32(smem);
    const int tid  = threadIdx.x;
    const int wid  = tid >> 5;
    const int lane = tid & 31;
    const int wm   = wid >> 1;        // 0..3 : 32-row M block
    const int wn   = wid & 1;         // 0..1 : 64-col N block
    const int g    = lane >> 2;
    const int tg   = lane & 3;

    if (tid == 0) {
        #pragma unroll
        for (int s = 0; s < STAGES; s++) {
            MBARRIER_INIT(MBAR_R(s), NTHREADS);
            MBARRIER_INIT(MBAR_D(s), NTHREADS);
        }
    }
    __syncthreads();

    const __nv_bfloat16* Arow = g_xbf + (size_t)blockIdx.y * BM * DIN;
    const __nv_bfloat16* Bcol = g_wbf + (size_t)blockIdx.x * BN;   // [K][N] native; CTA's n-slice

    // A: 128 rows x 8 vecs (swizzle ^(r&7));  B: 64 k-rows x 16 vecs (two-atom swizzle)
    // total 1024 + 1024 = 2048 vecs / 256 thr = 8 each
    auto load_stage = [&](int stage, int chunk) {
        const int k0 = chunk * BK;
        const uint32_t base = smem_base + STAGE0_OFF + stage * STAGE_BYTES;
        #pragma unroll
        for (int j = 0; j < 4; j++) {          // A: vecs 0..1023
            const int v  = tid + j * 256;
            const int r  = v >> 3;
            const int cc = v & 7;
            const uint32_t dst_off = (uint32_t)r * 128 + ((cc ^ (r & 7)) << 4);
            CP_ASYNC16(base + dst_off,
                       reinterpret_cast<const char*>(Arow + (size_t)r * DIN + k0) + cc * 16);
        }
        #pragma unroll
        for (int j = 0; j < 4; j++) {          // B: vecs 0..1023 (64 k-rows x 16 vecs)
            const int v  = tid + j * 256;
            const int r  = v >> 4;             // k-row 0..63
            const int cc = v & 15;             // 16B-vec within 256B row
            const uint32_t phys = (uint32_t)(((cc & 8) | ((cc & 7) ^ (r & 7))) << 4);
            CP_ASYNC16(base + A_STAGE + (uint32_t)r * 256 + phys,
                       reinterpret_cast<const char*>(Bcol + (size_t)(k0 + r) * DOUT) + cc * 16);
        }
    };

    float acc[2][8][4];
    #pragma unroll
    for (int mi = 0; mi < 2; mi++)
        #pragma unroll
        for (int ni = 0; ni < 8; ni++)
            #pragma unroll
            for (int q = 0; q < 4; q++) acc[mi][ni][q] = 0.f;

    // prologue: issue chunks 0 and 1
    load_stage(0, 0);
    CPASYNC_MBAR_ARRIVE_NOINC(MBAR_D(0));
    load_stage(1, 1);
    CPASYNC_MBAR_ARRIVE_NOINC(MBAR_D(1));

    // A fragment addressing (validated R8/R10)
    const int aRowL = wm * 32 + (lane & 15);
    const int aColL = lane >> 4;

    // B fragment addressing for ldmatrix.trans from [K][N] tile:
    //   lane L addresses k-row = L&15; n-col vec cc = wn*8 + np*2 + (L>>4)
    //   lane groups -> matrices: 0-7:(k0-7,n0-7)=r0, 8-15:(k8-15,n0-7)=r1,
    //                            16-23:(k0-7,n+8)=r2, 24-31:(k8-15,n+8)=r3
    //   swizzle constant across ks (ks*16 == 0 mod 8): addr(ks) = boff[np] + ks*16*256
    const int bKrow = lane & 15;
    uint32_t boff[4];
    #pragma unroll
    for (int np = 0; np < 4; np++) {
        const int cc = wn * 8 + np * 2 + (lane >> 4);
        const uint32_t phys = (uint32_t)(((cc & 8) | ((cc & 7) ^ (bKrow & 7))) << 4);
        boff[np] = (uint32_t)A_STAGE + (uint32_t)bKrow * 256 + phys;
    }

    for (int c = 0; c < NCHUNKS; c++) {
        // ---- producer: issue loads for chunk c+2 ----
        const int cc2 = c + 2;
        if (cc2 < NCHUNKS) {
            const int sI = cc2 % STAGES;
            if (cc2 >= STAGES) MBARRIER_WAIT_PARITY(MBAR_R(sI), ((cc2 - STAGES) / STAGES) & 1);
            load_stage(sI, cc2);
            CPASYNC_MBAR_ARRIVE_NOINC(MBAR_D(sI));
        }

        // ---- consumer: wait data for chunk c ----
        const int sC = c % STAGES;
        MBARRIER_WAIT_PARITY(MBAR_D(sC), (c / STAGES) & 1);

        const uint32_t sA = smem_base + STAGE0_OFF + sC * STAGE_BYTES;
        const uint32_t sBase = sA;   // boff includes A_STAGE

        // load ALL fragments for the chunk, then signal reads-done, then HMMA
        uint32_t a[4][2][4], b[4][8][2];
        #pragma unroll
        for (int ks = 0; ks < 4; ks++) {
            #pragma unroll
            for (int mi = 0; mi < 2; mi++) {
                const int r = aRowL + mi * 16;
                const int ccol = (aColL + ks * 2) ^ (r & 7);
                LDSM_X4(a[ks][mi][0], a[ks][mi][1], a[ks][mi][2], a[ks][mi][3],
                        sA + (uint32_t)r * 128 + (ccol << 4));
            }
            #pragma unroll
            for (int np = 0; np < 4; np++)
                LDSM_X4_T(b[ks][2 * np][0], b[ks][2 * np][1], b[ks][2 * np + 1][0], b[ks][2 * np + 1][1],
                          sBase + boff[np] + (uint32_t)ks * (16 * 256));
            if (ks == 3) MBARRIER_ARRIVE(MBAR_R(sC));   // all smem reads of this chunk issued
            #pragma unroll
            for (int mi = 0; mi < 2; mi++)
                #pragma unroll
                for (int ni = 0; ni < 8; ni++)
                    hmma_16816(acc[mi][ni], a[ks][mi][0], a[ks][mi][1], a[ks][mi][2], a[ks][mi][3],
                               b[ks][ni][0], b[ks][ni][1]);
        }
    }

    // -------- epilogue: + bias, float2 stores --------
    const int gm0 = blockIdx.y * BM + wm * 32;
    const int gn0 = blockIdx.x * BN + wn * 64;
    #pragma unroll
    for (int ni = 0; ni < 8; ni++) {
        const int col = gn0 + ni * 8 + tg * 2;
        const float2 bb = *reinterpret_cast<const float2*>(bias + col);
        #pragma unroll
        for (int mi = 0; mi < 2; mi++) {
            const int row0 = gm0 + mi * 16 + g;
            float2 o0, o1;
            o0.x = acc[mi][ni][0] + bb.x;
            o0.y = acc[mi][ni][1] + bb.y;
            o1.x = acc[mi][ni][2] + bb.x;
            o1.y = acc[mi][ni][3] + bb.y;
            *reinterpret_cast<float2*>(out + (size_t)row0 * DOUT + col)       = o0;
            *reinterpret_cast<float2*>(out + (size_t)(row0 + 8) * DOUT + col) = o1;
        }
    }
}

// ---------------- launch ----------------
extern "C" void kernel_launch(void* const* d_in, const int* in_sizes, int n_in,
                              void* d_out, int out_size) {
    const float* x    = (const float*)d_in[0];   // [4,2048,2048] fp32
    const float* w    = (const float*)d_in[1];   // [2048,2048] fp32
    const float* xs   = (const float*)d_in[2];   // scalar fp32
    const float* bias = (const float*)d_in[3];   // [2048] fp32
    float* out = (float*)d_out;

    prep_kernel<<<W_BLOCKS + QX_BLOCKS, 256>>>(x, w, xs);

    static int configured = 0;
    if (!configured) {
        cudaFuncSetAttribute(gemm_bf16_kernel, cudaFuncAttributeMaxDynamicSharedMemorySize, SMEM_TOTAL);
        configured = 1;
    }
    gemm_bf16_kernel<<<dim3(DOUT / BN, MTOT / BM), NTHREADS, SMEM_TOTAL>>>(bias, out);
}